// round 1
// baseline (speedup 1.0000x reference)
#include <cuda_runtime.h>

#define T_DIM 3
#define B_DIM 100000
#define D_DIM 128
#define NEG_SLOPE 0.01f

// One warp per (t, b) row. D=128 -> each lane owns 4 consecutive floats (float4).
// Single pass: load h_center row + 3 h_neigh rows + weights, compute the 5 dot
// products with one fused warp reduction, softmax over 4 scalars, then fused
// weighted sum and float4 store. Every input byte is touched exactly once.
__global__ __launch_bounds__(256, 8)
void attconv_kernel(const float4* __restrict__ h_center,   // (T*B*32) float4
                    const float4* __restrict__ h_neigh,    // (T*T*B*32) float4
                    const float4* __restrict__ att_w,      // (T*64) float4
                    const float*  __restrict__ att_b,      // (T)
                    float4* __restrict__ out)              // (T*B*32) float4
{
    const int gwarp = (blockIdx.x * blockDim.x + threadIdx.x) >> 5;  // = t*B + b
    const int lane  = threadIdx.x & 31;
    if (gwarp >= T_DIM * B_DIM) return;

    const int t = gwarp / B_DIM;
    const int b = gwarp - t * B_DIM;

    // float4-granular offsets (32 float4 per row of 128 floats)
    const int ctr_off = gwarp * 32 + lane;
    const int nb_base = (t * T_DIM * B_DIM + b) * 32 + lane;  // + n*B*32 per neighbor

    // Issue all independent loads up front (maximize MLP).
    const float4 ch = __ldg(h_center + ctr_off);
    const float4 n0 = __ldg(h_neigh + nb_base + 0 * B_DIM * 32);
    const float4 n1 = __ldg(h_neigh + nb_base + 1 * B_DIM * 32);
    const float4 n2 = __ldg(h_neigh + nb_base + 2 * B_DIM * 32);
    const float4 wh = __ldg(att_w + t * 64 + lane);        // w_h chunk
    const float4 we = __ldg(att_w + t * 64 + 32 + lane);   // w_e chunk
    const float bias = __ldg(att_b + t);

    // Per-lane partial dot products.
    float ph = ch.x * wh.x + ch.y * wh.y + ch.z * wh.z + ch.w * wh.w;
    float p0 = n0.x * we.x + n0.y * we.y + n0.z * we.z + n0.w * we.w;
    float p1 = n1.x * we.x + n1.y * we.y + n1.z * we.z + n1.w * we.w;
    float p2 = n2.x * we.x + n2.y * we.y + n2.z * we.z + n2.w * we.w;
    float p3 = ch.x * we.x + ch.y * we.y + ch.z * we.z + ch.w * we.w;

    // Warp-wide reduction of all 5 partials.
    #pragma unroll
    for (int off = 16; off > 0; off >>= 1) {
        ph += __shfl_xor_sync(0xFFFFFFFFu, ph, off);
        p0 += __shfl_xor_sync(0xFFFFFFFFu, p0, off);
        p1 += __shfl_xor_sync(0xFFFFFFFFu, p1, off);
        p2 += __shfl_xor_sync(0xFFFFFFFFu, p2, off);
        p3 += __shfl_xor_sync(0xFFFFFFFFu, p3, off);
    }

    // scores = score_e + score_h + bias, then LeakyReLU.
    float s0 = p0 + ph + bias;
    float s1 = p1 + ph + bias;
    float s2 = p2 + ph + bias;
    float s3 = p3 + ph + bias;
    s0 = (s0 >= 0.f) ? s0 : NEG_SLOPE * s0;
    s1 = (s1 >= 0.f) ? s1 : NEG_SLOPE * s1;
    s2 = (s2 >= 0.f) ? s2 : NEG_SLOPE * s2;
    s3 = (s3 >= 0.f) ? s3 : NEG_SLOPE * s3;

    // Softmax over the 4 candidates (neighbors 0..2, center last).
    float m = fmaxf(fmaxf(s0, s1), fmaxf(s2, s3));
    float e0 = __expf(s0 - m);
    float e1 = __expf(s1 - m);
    float e2 = __expf(s2 - m);
    float e3 = __expf(s3 - m);
    float inv = 1.0f / (e0 + e1 + e2 + e3);
    float a0 = e0 * inv, a1 = e1 * inv, a2 = e2 * inv, a3 = e3 * inv;

    // Weighted sum (emd order: [n0, n1, n2, center]).
    float4 o;
    o.x = a0 * n0.x + a1 * n1.x + a2 * n2.x + a3 * ch.x;
    o.y = a0 * n0.y + a1 * n1.y + a2 * n2.y + a3 * ch.y;
    o.z = a0 * n0.z + a1 * n1.z + a2 * n2.z + a3 * ch.z;
    o.w = a0 * n0.w + a1 * n1.w + a2 * n2.w + a3 * ch.w;

    out[ctr_off] = o;
}

extern "C" void kernel_launch(void* const* d_in, const int* in_sizes, int n_in,
                              void* d_out, int out_size) {
    const float4* h_center = (const float4*)d_in[0];
    const float4* h_neigh  = (const float4*)d_in[1];
    const float4* att_w    = (const float4*)d_in[2];
    const float*  att_b    = (const float*)d_in[3];
    float4* out = (float4*)d_out;

    const int total_warps = T_DIM * B_DIM;              // 300000
    const int threads = 256;                            // 8 warps/block
    const int blocks = (total_warps * 32 + threads - 1) / threads;  // 37500

    attconv_kernel<<<blocks, threads>>>(h_center, h_neigh, att_w, att_b, out);
}